// round 1
// baseline (speedup 1.0000x reference)
#include <cuda_runtime.h>

#define R_TOTAL 32768   // B*N rows
#define KCODES  8192
#define DDIM    512
#define BM 128
#define BN 128
#define BK 16

// Scratch (no allocations allowed)
__device__ float g_rowA[R_TOTAL];
__device__ float g_enorm[KCODES];
__device__ float g_rowpart[R_TOTAL];
__device__ int   g_codes[R_TOTAL];

// ---------------------------------------------------------------------------
// Row sum-of-squares, emulating XLA:CPU NEON 4-lane reduce:
//   lane_j = sequential sum of x[4i+j]^2  (separate mul & add roundings)
//   A = (l0+l2) + (l1+l3)
// which = 0 -> z rows into g_rowA, which = 1 -> embed rows into g_enorm
// ---------------------------------------------------------------------------
__global__ void rownorm_kernel(const float* __restrict__ z,
                               const float* __restrict__ embed,
                               int which) {
    int gid  = blockIdx.x * blockDim.x + threadIdx.x;
    int row  = gid >> 2;
    int lane = gid & 3;
    int nrows = (which == 0) ? R_TOTAL : KCODES;
    if (row >= nrows) return;
    const float* p = ((which == 0) ? z : embed) + (size_t)row * DDIM;
    float acc = 0.0f;
    #pragma unroll 8
    for (int i = lane; i < DDIM; i += 4) {
        float v = p[i];
        acc = __fadd_rn(acc, __fmul_rn(v, v));   // no FMA contraction
    }
    // combine (l0+l2)+(l1+l3)
    float o  = __shfl_xor_sync(0xFFFFFFFF, acc, 2);
    float s  = __fadd_rn(acc, o);
    float o2 = __shfl_xor_sync(0xFFFFFFFF, s, 1);
    float A  = __fadd_rn(s, o2);
    if (lane == 0) {
        if (which == 0) g_rowA[row]  = A;
        else            g_enorm[row] = A;
    }
}

// ---------------------------------------------------------------------------
// Fused distance-GEMM + argmin.
// dist(row, code) = fl( fl(A_row - 2*dot) + C_code ), fp32 FMA dot.
// 256 threads (16x16), 8x8 micro-tile, BM x BN x BK = 128x128x16.
// ---------------------------------------------------------------------------
__global__ void __launch_bounds__(256) argmin_kernel(
    const float* __restrict__ z,
    const float* __restrict__ embed,
    float* __restrict__ codes_f)   // may be null
{
    __shared__ float zs[BK][BM];
    __shared__ float es[BK][BN];
    __shared__ float sval[BM][16];
    __shared__ int   sidx[BM][16];

    const int row0 = blockIdx.x * BM;
    const int tid  = threadIdx.x;
    const int tx   = tid & 15;
    const int ty   = tid >> 4;

    float rA[8];
    #pragma unroll
    for (int i = 0; i < 8; i++) rA[i] = g_rowA[row0 + ty * 8 + i];

    float bestv[8];
    int   besti[8];
    #pragma unroll
    for (int i = 0; i < 8; i++) { bestv[i] = 3.402823466e+38f; besti[i] = 0; }

    for (int nt = 0; nt < KCODES / BN; nt++) {
        const int n0 = nt * BN;
        float acc[8][8];
        #pragma unroll
        for (int i = 0; i < 8; i++)
            #pragma unroll
            for (int j = 0; j < 8; j++) acc[i][j] = 0.0f;

        for (int kt = 0; kt < DDIM / BK; kt++) {
            const int k0 = kt * BK;
            #pragma unroll
            for (int u = 0; u < 2; u++) {
                int idx = tid + u * 256;         // 0..511
                int m   = idx >> 2;
                int kq  = idx & 3;
                float4 v = *(const float4*)(z + (size_t)(row0 + m) * DDIM + k0 + kq * 4);
                zs[kq * 4 + 0][m] = v.x;
                zs[kq * 4 + 1][m] = v.y;
                zs[kq * 4 + 2][m] = v.z;
                zs[kq * 4 + 3][m] = v.w;
                float4 w = *(const float4*)(embed + (size_t)(n0 + m) * DDIM + k0 + kq * 4);
                es[kq * 4 + 0][m] = w.x;
                es[kq * 4 + 1][m] = w.y;
                es[kq * 4 + 2][m] = w.z;
                es[kq * 4 + 3][m] = w.w;
            }
            __syncthreads();
            #pragma unroll
            for (int k = 0; k < BK; k++) {
                float a[8], b[8];
                *(float4*)(a)     = *(const float4*)&zs[k][ty * 8];
                *(float4*)(a + 4) = *(const float4*)&zs[k][ty * 8 + 4];
                *(float4*)(b)     = *(const float4*)&es[k][tx * 8];
                *(float4*)(b + 4) = *(const float4*)&es[k][tx * 8 + 4];
                #pragma unroll
                for (int i = 0; i < 8; i++)
                    #pragma unroll
                    for (int j = 0; j < 8; j++)
                        acc[i][j] = fmaf(a[i], b[j], acc[i][j]);
            }
            __syncthreads();
        }

        // Epilogue for this code tile: quantized dist + running lex-min.
        float en[8];
        *(float4*)(en)     = *(const float4*)(g_enorm + n0 + tx * 8);
        *(float4*)(en + 4) = *(const float4*)(g_enorm + n0 + tx * 8 + 4);
        #pragma unroll
        for (int i = 0; i < 8; i++) {
            #pragma unroll
            for (int j = 0; j < 8; j++) {
                float B    = 2.0f * acc[i][j];                 // exact
                float t    = __fadd_rn(rA[i], -B);             // fl(A - B)
                float dist = __fadd_rn(t, en[j]);              // fl(t + C)
                int   n    = n0 + tx * 8 + j;
                if (dist < bestv[i]) { bestv[i] = dist; besti[i] = n; }
            }
        }
    }

    #pragma unroll
    for (int i = 0; i < 8; i++) {
        sval[ty * 8 + i][tx] = bestv[i];
        sidx[ty * 8 + i][tx] = besti[i];
    }
    __syncthreads();
    if (tid < BM) {
        float bv = sval[tid][0];
        int   bi = sidx[tid][0];
        #pragma unroll
        for (int t = 1; t < 16; t++) {
            float v  = sval[tid][t];
            int   ix = sidx[tid][t];
            if (v < bv || (v == bv && ix < bi)) { bv = v; bi = ix; }
        }
        g_codes[row0 + tid] = bi;
        if (codes_f) codes_f[row0 + tid] = (float)bi;
    }
}

// ---------------------------------------------------------------------------
// Gather z_q = embed[code] + per-row partial of sum((z - z_q)^2).
// One block (128 threads) per row; thread t handles float4 at t*4.
// ---------------------------------------------------------------------------
__global__ void gather_kernel(const float* __restrict__ z,
                              const float* __restrict__ embed,
                              float* __restrict__ out_zq) {
    const int row = blockIdx.x;
    const int t   = threadIdx.x;
    const int c   = g_codes[row];
    float4 e  = *(const float4*)(embed + (size_t)c * DDIM + t * 4);
    float4 zz = *(const float4*)(z + (size_t)row * DDIM + t * 4);
    *(float4*)(out_zq + (size_t)row * DDIM + t * 4) = e;
    float dx = zz.x - e.x, dy = zz.y - e.y, dz = zz.z - e.z, dw = zz.w - e.w;
    float s = dx * dx + dy * dy + dz * dz + dw * dw;
    __shared__ float red[128];
    red[t] = s;
    __syncthreads();
    #pragma unroll
    for (int o = 64; o > 0; o >>= 1) {
        if (t < o) red[t] += red[t + o];
        __syncthreads();
    }
    if (t == 0) g_rowpart[row] = red[0];
}

__global__ void loss_kernel(float* __restrict__ out_loss) {
    const int t = threadIdx.x;
    float s = 0.0f;
    for (int i = t; i < R_TOTAL; i += 1024) s += g_rowpart[i];
    __shared__ float red[1024];
    red[t] = s;
    __syncthreads();
    for (int o = 512; o > 0; o >>= 1) {
        if (t < o) red[t] += red[t + o];
        __syncthreads();
    }
    if (t == 0) out_loss[0] = 0.1f * (red[0] / 16777216.0f);
}

// ---------------------------------------------------------------------------
extern "C" void kernel_launch(void* const* d_in, const int* in_sizes, int n_in,
                              void* d_out, int out_size) {
    const float* z     = (const float*)d_in[0];   // (8,4096,512) f32
    const float* embed = (const float*)d_in[1];   // (8192,512) f32
    float* out = (float*)d_out;

    const long long ZQ_ELEMS = (long long)R_TOTAL * DDIM;      // 16777216
    float* out_zq    = out;
    float* out_codes = 0;
    float* out_loss  = 0;
    if ((long long)out_size >= ZQ_ELEMS + R_TOTAL + 1) {
        out_codes = out + ZQ_ELEMS;
        out_loss  = out + ZQ_ELEMS + R_TOTAL;
    }

    // row norms: z (32768 rows x 4 lanes) and embed (8192 rows x 4 lanes)
    rownorm_kernel<<<(R_TOTAL * 4 + 255) / 256, 256>>>(z, embed, 0);
    rownorm_kernel<<<(KCODES * 4 + 255) / 256, 256>>>(z, embed, 1);

    argmin_kernel<<<R_TOTAL / BM, 256>>>(z, embed, out_codes);

    gather_kernel<<<R_TOTAL, 128>>>(z, embed, out_zq);

    if (out_loss) loss_kernel<<<1, 1024>>>(out_loss);
}

// round 2
// speedup vs baseline: 4.7466x; 4.7466x over previous
#include <cuda_runtime.h>
#include <cuda_bf16.h>
#include <cstdint>

#define R_TOTAL 32768   // B*N rows
#define KCODES  8192
#define DDIM    512
#define NTILES  512     // 16-wide code tiles for screening
#define MARGIN  5e-4f

// ---------------- static scratch (no allocations allowed) ----------------
__device__ float         g_rowA[R_TOTAL];
__device__ float         g_enorm[KCODES];
__device__ float         g_rowpart[R_TOTAL];
__device__ int           g_codes[R_TOTAL];
__device__ __nv_bfloat16 g_zb[(size_t)R_TOTAL * DDIM];   // 32 MB
__device__ __nv_bfloat16 g_eb[(size_t)KCODES * DDIM];    //  8 MB
__device__ float         g_tilemin[(size_t)R_TOTAL * NTILES]; // 64 MB

__device__ __forceinline__ uint32_t smaddr(const void* p) {
    return (uint32_t)__cvta_generic_to_shared(p);
}

// ---------------------------------------------------------------------------
// Row sum-of-squares, emulating XLA:CPU NEON 4-lane reduce (unchanged, passing)
// ---------------------------------------------------------------------------
__global__ void rownorm_kernel(const float* __restrict__ z,
                               const float* __restrict__ embed,
                               int which) {
    int gid  = blockIdx.x * blockDim.x + threadIdx.x;
    int row  = gid >> 2;
    int lane = gid & 3;
    int nrows = (which == 0) ? R_TOTAL : KCODES;
    if (row >= nrows) return;
    const float* p = ((which == 0) ? z : embed) + (size_t)row * DDIM;
    float acc = 0.0f;
    #pragma unroll 8
    for (int i = lane; i < DDIM; i += 4) {
        float v = p[i];
        acc = __fadd_rn(acc, __fmul_rn(v, v));
    }
    float o  = __shfl_xor_sync(0xFFFFFFFF, acc, 2);
    float s  = __fadd_rn(acc, o);
    float o2 = __shfl_xor_sync(0xFFFFFFFF, s, 1);
    float A  = __fadd_rn(s, o2);
    if (lane == 0) {
        if (which == 0) g_rowA[row]  = A;
        else            g_enorm[row] = A;
    }
}

// ---------------------------------------------------------------------------
// fp32 -> bf16 conversion of z and embed
// ---------------------------------------------------------------------------
__global__ void convert_kernel(const float* __restrict__ z,
                               const float* __restrict__ embed) {
    const int NZ = R_TOTAL * DDIM / 4;
    const int NE = KCODES * DDIM / 4;
    int i = blockIdx.x * blockDim.x + threadIdx.x;
    if (i < NZ) {
        float4 v = ((const float4*)z)[i];
        ((__nv_bfloat162*)g_zb)[i * 2 + 0] = __floats2bfloat162_rn(v.x, v.y);
        ((__nv_bfloat162*)g_zb)[i * 2 + 1] = __floats2bfloat162_rn(v.z, v.w);
    } else if (i < NZ + NE) {
        int j = i - NZ;
        float4 v = ((const float4*)embed)[j];
        ((__nv_bfloat162*)g_eb)[j * 2 + 0] = __floats2bfloat162_rn(v.x, v.y);
        ((__nv_bfloat162*)g_eb)[j * 2 + 1] = __floats2bfloat162_rn(v.z, v.w);
    }
}

// ---------------------------------------------------------------------------
// Screening GEMM: bf16 mma.sync, fp32 accum. 128x128 block tile, BK=32,
// double-buffered cp.async. Epilogue: min of approx dist per (row, 16-code tile).
// ---------------------------------------------------------------------------
#define GBM 128
#define GBN 128
#define GBK 32
#define SKEW 8

__global__ void __launch_bounds__(256) screen_gemm_kernel() {
    __shared__ __nv_bfloat16 As[2][GBM][GBK + SKEW];
    __shared__ __nv_bfloat16 Bs[2][GBN][GBK + SKEW];

    const int tid   = threadIdx.x;
    const int wid   = tid >> 5;
    const int lane  = tid & 31;
    const int warpY = wid >> 1;   // 0..3 : 32-row group
    const int warpX = wid & 1;    // 0..1 : 64-col group
    const int row0  = blockIdx.x * GBM;
    const int n0    = blockIdx.y * GBN;

    float acc[2][8][4];
    #pragma unroll
    for (int m = 0; m < 2; m++)
        #pragma unroll
        for (int n = 0; n < 8; n++)
            #pragma unroll
            for (int p = 0; p < 4; p++) acc[m][n][p] = 0.0f;

    // global->shared chunk mapping: chunk c in [0,512): row=c>>2, k-quarter=c&3
    const int ca = tid, cb = tid + 256;
    const int ra = ca >> 2, ka = (ca & 3) * 8;
    const int rb = cb >> 2, kb = (cb & 3) * 8;

#define LOAD_TILE(kt, buf) do {                                                   \
    int k0_ = (kt) * GBK;                                                         \
    asm volatile("cp.async.cg.shared.global [%0], [%1], 16;" ::                   \
        "r"(smaddr(&As[buf][ra][ka])),                                            \
        "l"(g_zb + (size_t)(row0 + ra) * DDIM + k0_ + ka));                       \
    asm volatile("cp.async.cg.shared.global [%0], [%1], 16;" ::                   \
        "r"(smaddr(&Bs[buf][ra][ka])),                                            \
        "l"(g_eb + (size_t)(n0 + ra) * DDIM + k0_ + ka));                         \
    asm volatile("cp.async.cg.shared.global [%0], [%1], 16;" ::                   \
        "r"(smaddr(&As[buf][rb][kb])),                                            \
        "l"(g_zb + (size_t)(row0 + rb) * DDIM + k0_ + kb));                       \
    asm volatile("cp.async.cg.shared.global [%0], [%1], 16;" ::                   \
        "r"(smaddr(&Bs[buf][rb][kb])),                                            \
        "l"(g_eb + (size_t)(n0 + rb) * DDIM + k0_ + kb));                         \
    asm volatile("cp.async.commit_group;");                                       \
} while (0)

    // ldmatrix per-thread addressing
    const int i8 = lane & 7, q = lane >> 3;
    const int a_row = warpY * 32 + (q & 1) * 8 + i8;  // + m*16
    const int a_col = (q >> 1) * 8;                   // + ks
    const int b_row = warpX * 64 + i8;                // + n*8
    const int b_col = (q & 1) * 8;                    // + ks

    LOAD_TILE(0, 0);

    const int NKT = DDIM / GBK;  // 16
    for (int kt = 0; kt < NKT; kt++) {
        const int buf = kt & 1;
        if (kt + 1 < NKT) {
            LOAD_TILE(kt + 1, (kt + 1) & 1);
            asm volatile("cp.async.wait_group 1;");
        } else {
            asm volatile("cp.async.wait_group 0;");
        }
        __syncthreads();

        #pragma unroll
        for (int ks = 0; ks < GBK; ks += 16) {
            uint32_t a[2][4], b[8][2];
            #pragma unroll
            for (int m = 0; m < 2; m++) {
                uint32_t addr = smaddr(&As[buf][a_row + m * 16][ks + a_col]);
                asm volatile("ldmatrix.sync.aligned.m8n8.x4.shared.b16 {%0,%1,%2,%3}, [%4];"
                    : "=r"(a[m][0]), "=r"(a[m][1]), "=r"(a[m][2]), "=r"(a[m][3])
                    : "r"(addr));
            }
            #pragma unroll
            for (int n = 0; n < 8; n++) {
                uint32_t addr = smaddr(&Bs[buf][b_row + n * 8][ks + b_col]);
                asm volatile("ldmatrix.sync.aligned.m8n8.x2.shared.b16 {%0,%1}, [%2];"
                    : "=r"(b[n][0]), "=r"(b[n][1])
                    : "r"(addr));
            }
            #pragma unroll
            for (int m = 0; m < 2; m++)
                #pragma unroll
                for (int n = 0; n < 8; n++) {
                    asm volatile(
                        "mma.sync.aligned.m16n8k16.row.col.f32.bf16.bf16.f32 "
                        "{%0,%1,%2,%3}, {%4,%5,%6,%7}, {%8,%9}, {%0,%1,%2,%3};"
                        : "+f"(acc[m][n][0]), "+f"(acc[m][n][1]),
                          "+f"(acc[m][n][2]), "+f"(acc[m][n][3])
                        : "r"(a[m][0]), "r"(a[m][1]), "r"(a[m][2]), "r"(a[m][3]),
                          "r"(b[n][0]), "r"(b[n][1]));
                }
        }
        __syncthreads();
    }
#undef LOAD_TILE

    // ---- epilogue: approx dist + per-(row, 16-code subtile) min ----
    const int g  = lane >> 2;   // row group 0..7
    const int qc = lane & 3;    // col pair

    float en[8][2];
    #pragma unroll
    for (int n = 0; n < 8; n++) {
        int col = n0 + warpX * 64 + n * 8 + qc * 2;
        en[n][0] = g_enorm[col];
        en[n][1] = g_enorm[col + 1];
    }

    #pragma unroll
    for (int m = 0; m < 2; m++) {
        #pragma unroll
        for (int h = 0; h < 2; h++) {
            int grow = row0 + warpY * 32 + m * 16 + g + h * 8;
            float Ar = g_rowA[grow];
            #pragma unroll
            for (int s = 0; s < 4; s++) {
                float v = 3.402823466e+38f;
                #pragma unroll
                for (int nn = 0; nn < 2; nn++) {
                    int n = s * 2 + nn;
                    #pragma unroll
                    for (int p = 0; p < 2; p++) {
                        float d = Ar - 2.0f * acc[m][n][h * 2 + p] + en[n][p];
                        v = fminf(v, d);
                    }
                }
                v = fminf(v, __shfl_xor_sync(0xFFFFFFFF, v, 1));
                v = fminf(v, __shfl_xor_sync(0xFFFFFFFF, v, 2));
                if (qc == 0)
                    g_tilemin[(size_t)grow * NTILES + blockIdx.y * 8 + warpX * 4 + s] = v;
            }
        }
    }
}

// ---------------------------------------------------------------------------
// Rescore: per row, select tiles within MARGIN of the screened min, recompute
// those codes with reference-exact fp32 rounding (sequential ascending-k fmaf),
// lexicographic (val, idx) argmin. One warp per row.
// ---------------------------------------------------------------------------
__global__ void __launch_bounds__(256) rescore_kernel(
    const float* __restrict__ z,
    const float* __restrict__ embed,
    float* __restrict__ codes_f)   // may be null
{
    const int wid  = threadIdx.x >> 5;
    const int lane = threadIdx.x & 31;
    const int row  = blockIdx.x * 8 + wid;

    float tm[16];
    #pragma unroll
    for (int j = 0; j < 16; j++)
        tm[j] = g_tilemin[(size_t)row * NTILES + lane + 32 * j];

    float rmin = tm[0];
    #pragma unroll
    for (int j = 1; j < 16; j++) rmin = fminf(rmin, tm[j]);
    #pragma unroll
    for (int o = 16; o > 0; o >>= 1)
        rmin = fminf(rmin, __shfl_xor_sync(0xFFFFFFFF, rmin, o));

    const float thr = rmin + MARGIN;
    const float A   = g_rowA[row];
    const float4* z4 = (const float4*)(z + (size_t)row * DDIM);

    float bestv = 3.402823466e+38f;
    int   besti = 0x7FFFFFFF;

    for (int j = 0; j < 16; j++) {
        unsigned mask = __ballot_sync(0xFFFFFFFF, tm[j] <= thr);
        while (mask) {
            int b = __ffs(mask) - 1;
            mask &= mask - 1;
            int tile = b + 32 * j;
            if (lane < 16) {
                int c = tile * 16 + lane;
                const float4* e4 = (const float4*)(embed + (size_t)c * DDIM);
                float dot = 0.0f;
                #pragma unroll 8
                for (int k = 0; k < DDIM / 4; k++) {
                    float4 ev = e4[k];
                    float4 zv = z4[k];
                    dot = fmaf(zv.x, ev.x, dot);
                    dot = fmaf(zv.y, ev.y, dot);
                    dot = fmaf(zv.z, ev.z, dot);
                    dot = fmaf(zv.w, ev.w, dot);
                }
                float B2   = 2.0f * dot;
                float tt   = __fadd_rn(A, -B2);
                float dist = __fadd_rn(tt, g_enorm[c]);
                if (dist < bestv || (dist == bestv && c < besti)) {
                    bestv = dist;
                    besti = c;
                }
            }
        }
    }

    #pragma unroll
    for (int o = 16; o > 0; o >>= 1) {
        float ov = __shfl_xor_sync(0xFFFFFFFF, bestv, o);
        int   oi = __shfl_xor_sync(0xFFFFFFFF, besti, o);
        if (ov < bestv || (ov == bestv && oi < besti)) { bestv = ov; besti = oi; }
    }
    if (lane == 0) {
        g_codes[row] = besti;
        if (codes_f) codes_f[row] = (float)besti;
    }
}

// ---------------------------------------------------------------------------
// Gather z_q = embed[code] + per-row partial of sum((z - z_q)^2). (unchanged)
// ---------------------------------------------------------------------------
__global__ void gather_kernel(const float* __restrict__ z,
                              const float* __restrict__ embed,
                              float* __restrict__ out_zq) {
    const int row = blockIdx.x;
    const int t   = threadIdx.x;
    const int c   = g_codes[row];
    float4 e  = *(const float4*)(embed + (size_t)c * DDIM + t * 4);
    float4 zz = *(const float4*)(z + (size_t)row * DDIM + t * 4);
    *(float4*)(out_zq + (size_t)row * DDIM + t * 4) = e;
    float dx = zz.x - e.x, dy = zz.y - e.y, dz = zz.z - e.z, dw = zz.w - e.w;
    float s = dx * dx + dy * dy + dz * dz + dw * dw;
    __shared__ float red[128];
    red[t] = s;
    __syncthreads();
    #pragma unroll
    for (int o = 64; o > 0; o >>= 1) {
        if (t < o) red[t] += red[t + o];
        __syncthreads();
    }
    if (t == 0) g_rowpart[row] = red[0];
}

__global__ void loss_kernel(float* __restrict__ out_loss) {
    const int t = threadIdx.x;
    float s = 0.0f;
    for (int i = t; i < R_TOTAL; i += 1024) s += g_rowpart[i];
    __shared__ float red[1024];
    red[t] = s;
    __syncthreads();
    for (int o = 512; o > 0; o >>= 1) {
        if (t < o) red[t] += red[t + o];
        __syncthreads();
    }
    if (t == 0) out_loss[0] = 0.1f * (red[0] / 16777216.0f);
}

// ---------------------------------------------------------------------------
extern "C" void kernel_launch(void* const* d_in, const int* in_sizes, int n_in,
                              void* d_out, int out_size) {
    const float* z     = (const float*)d_in[0];   // (8,4096,512) f32
    const float* embed = (const float*)d_in[1];   // (8192,512) f32
    float* out = (float*)d_out;

    const long long ZQ_ELEMS = (long long)R_TOTAL * DDIM;
    float* out_zq    = out;
    float* out_codes = 0;
    float* out_loss  = 0;
    if ((long long)out_size >= ZQ_ELEMS + R_TOTAL + 1) {
        out_codes = out + ZQ_ELEMS;
        out_loss  = out + ZQ_ELEMS + R_TOTAL;
    }

    const int NCONV = (R_TOTAL * DDIM + KCODES * DDIM) / 4;
    convert_kernel<<<(NCONV + 255) / 256, 256>>>(z, embed);

    rownorm_kernel<<<(R_TOTAL * 4 + 255) / 256, 256>>>(z, embed, 0);
    rownorm_kernel<<<(KCODES * 4 + 255) / 256, 256>>>(z, embed, 1);

    dim3 gg(R_TOTAL / GBM, KCODES / GBN);   // (256, 64)
    screen_gemm_kernel<<<gg, 256>>>();

    rescore_kernel<<<R_TOTAL / 8, 256>>>(z, embed, out_codes);

    gather_kernel<<<R_TOTAL, 128>>>(z, embed, out_zq);

    if (out_loss) loss_kernel<<<1, 1024>>>(out_loss);
}